// round 14
// baseline (speedup 1.0000x reference)
#include <cuda_runtime.h>
#include <cuda_fp16.h>
#include <cstdint>

#define B_     2
#define S_     2048
#define E_     256
#define H_     8
#define DH_    256
#define INNER_ 2048
#define QKVW_  (3*INNER_)   // 6144
#define DFF_   1024
#define BSZ    (B_*S_)
#define EPS_   1e-6f

typedef __half h16;

// ---------------- device scratch ----------------
__device__ h16   g_xh [(size_t)BSZ * E_];
__device__ h16   g_wqkvT[(size_t)QKVW_ * E_];
__device__ h16   g_woT [(size_t)E_ * INNER_];
__device__ h16   g_w1T [(size_t)DFF_ * E_];
__device__ h16   g_w2T [(size_t)E_ * DFF_];
__device__ h16   g_qkvh[(size_t)BSZ * QKVW_];     // q|k|v packed, ld=6144
__device__ h16   g_vth[(size_t)BSZ * INNER_];     // V^T per (b,h): [B*H][DH][S]
__device__ h16   g_oh [(size_t)BSZ * INNER_];
__device__ float g_part[(size_t)4 * BSZ * E_];    // split-K partials
__device__ float g_hf [(size_t)BSZ * E_];
__device__ h16   g_hh [(size_t)BSZ * E_];
__device__ h16   g_ffh[(size_t)BSZ * DFF_];

// ---------------- helpers ----------------
__device__ __forceinline__ uint32_t smem_u32(const void* p) {
    uint32_t a;
    asm("{ .reg .u64 t; cvta.to.shared.u64 t, %1; cvt.u32.u64 %0, t; }"
        : "=r"(a) : "l"(p));
    return a;
}
__device__ __forceinline__ void ldsm_x4(uint32_t* r, uint32_t a) {
    asm volatile("ldmatrix.sync.aligned.m8n8.x4.shared.b16 {%0,%1,%2,%3}, [%4];"
                 : "=r"(r[0]), "=r"(r[1]), "=r"(r[2]), "=r"(r[3]) : "r"(a));
}
__device__ __forceinline__ void mma16816(float* c, const uint32_t* a,
                                         uint32_t b0, uint32_t b1) {
    asm volatile(
        "mma.sync.aligned.m16n8k16.row.col.f32.f16.f16.f32 "
        "{%0,%1,%2,%3}, {%4,%5,%6,%7}, {%8,%9}, {%0,%1,%2,%3};"
        : "+f"(c[0]), "+f"(c[1]), "+f"(c[2]), "+f"(c[3])
        : "r"(a[0]), "r"(a[1]), "r"(a[2]), "r"(a[3]), "r"(b0), "r"(b1));
}
#define CP16(dst, src) \
    asm volatile("cp.async.cg.shared.global [%0], [%1], 16;" :: "r"(dst), "l"(src) : "memory")
#define CP_COMMIT  asm volatile("cp.async.commit_group;" ::: "memory")
#define CP_WAIT0   asm volatile("cp.async.wait_group 0;" ::: "memory")
#define CP_WAIT1   asm volatile("cp.async.wait_group 1;" ::: "memory")
#define CP_WAIT2   asm volatile("cp.async.wait_group 2;" ::: "memory")

__device__ __forceinline__ uint32_t packh2(float x, float y) {
    __half2 t = __floats2half2_rn(x, y);
    return *(uint32_t*)&t;
}

// ================= flash attention, KVBLK=64, ping-pong QK/softmax =========
// grid (S_/128, B_*H_), 256 thr (8 warps x m16). Q resident (64KB),
// K + V double-buffered at 32KB slots. Iter i: QK(i+1) issued before
// softmax(i) so the tensor pipe overlaps the MUFU/FMA softmax phase.
#define QBLK   128
#define KVBLK  64
#define NKVT   (S_/KVBLK)      // 32
#define FO_K   65536           // 2 slots x 32768
#define FO_V   131072          // 2 slots x 32768
#define F_SMEM 196608

__global__ void __launch_bounds__(256)
flash_kernel(const h16* __restrict__ qkvh,
             const h16* __restrict__ vth_g,
             h16* __restrict__ oh_g)
{
    extern __shared__ __align__(128) char sm[];
    const uint32_t sb = smem_u32(sm);
    const int tid = threadIdx.x, wid = tid >> 5, lane = tid & 31;
    const int bh = blockIdx.y;
    const int b = bh >> 3, hd = bh & 7;
    const int q0 = blockIdx.x * QBLK;

    auto load_k = [&](int kv0, uint32_t slot) {      // 64 rows x 512B
        #pragma unroll
        for (int it = 0; it < 8; it++) {
            int c = tid + it * 256;
            int row = c >> 5, kc = c & 31;
            const h16* src = qkvh
                + ((size_t)(b * S_ + kv0 + row) * QKVW_ + 2048 + hd * 256 + kc * 8);
            CP16(slot + row * 512 + (uint32_t)((kc ^ (row & 7)) << 4), src);
        }
    };
    auto load_v = [&](int kv0, uint32_t slot) {      // 256 rows x 128B
        #pragma unroll
        for (int it = 0; it < 8; it++) {
            int c = tid + it * 256;
            int row = c >> 3, kc = c & 7;
            const h16* src = vth_g
                + ((size_t)bh * DH_ * S_ + (size_t)row * S_ + kv0 + kc * 8);
            CP16(slot + row * 128 + (uint32_t)((kc ^ (row & 7)) << 4), src);
        }
    };

    // prologue groups: P1={Q,K0,V0}, {K1}, {V1}
    #pragma unroll
    for (int it = 0; it < 16; it++) {                 // Q: 128 rows x 512B
        int c = tid + it * 256;
        int row = c >> 5, kc = c & 31;
        const h16* src = qkvh
            + ((size_t)(b * S_ + q0 + row) * QKVW_ + hd * 256 + kc * 8);
        CP16(sb + row * 512 + (uint32_t)((kc ^ (row & 7)) << 4), src);
    }
    load_k(0, sb + FO_K);
    load_v(0, sb + FO_V);
    CP_COMMIT;
    load_k(KVBLK, sb + FO_K + 32768);
    CP_COMMIT;
    load_v(KVBLK, sb + FO_V + 32768);
    CP_COMMIT;

    const int wm    = wid * 16;
    const int a_row = wm + (lane & 15);
    const uint32_t a_rowoff = (uint32_t)(a_row * 512);
    const int a_r7  = a_row & 7;
    const int a_hb  = lane >> 4;
    const int b_row = (lane & 7) + ((lane >> 4) & 1) * 8;
    const int b_kb  = (lane >> 3) & 1;

    float o[32][4];
    #pragma unroll
    for (int i = 0; i < 32; i++) { o[i][0]=0.f; o[i][1]=0.f; o[i][2]=0.f; o[i][3]=0.f; }
    float m0 = -1e30f, m1 = -1e30f, l0 = 0.f, l1 = 0.f;

    // S(tile) = Qh Kh^T  into register buffer sn
    auto qk_tile = [&](int t, float (&sn)[8][4]) {
        const uint32_t kbs = sb + FO_K + (uint32_t)((t & 1) * 32768);
        #pragma unroll
        for (int nt = 0; nt < 8; nt++) { sn[nt][0]=0.f; sn[nt][1]=0.f; sn[nt][2]=0.f; sn[nt][3]=0.f; }
        #pragma unroll
        for (int ks = 0; ks < 16; ks++) {
            const uint32_t aq = a_rowoff + (uint32_t)((((2 * ks + a_hb) ^ a_r7) << 4));
            uint32_t ah4[4];
            ldsm_x4(ah4, sb + aq);
            uint32_t kh4[4][4];
            #pragma unroll
            for (int g2 = 0; g2 < 4; g2++) {
                const int row = g2 * 16 + b_row;
                const uint32_t off = (uint32_t)(row * 512 + (((2 * ks + b_kb) ^ (row & 7)) << 4));
                ldsm_x4(kh4[g2], kbs + off);
            }
            #pragma unroll
            for (int nt = 0; nt < 8; nt++)
                mma16816(sn[nt], ah4, kh4[nt >> 1][(nt & 1) * 2], kh4[nt >> 1][(nt & 1) * 2 + 1]);
        }
    };

    CP_WAIT2;              // P1 landed (Q, K0, V0)
    __syncthreads();

    float sA[8][4], sB[8][4];
    qk_tile(0, sA);

    auto step = [&](int i, float (&scur)[8][4], float (&snext)[8][4]) {
        if (i + 1 < NKVT) { CP_WAIT1; } else { CP_WAIT0; }   // K(i+1), V(i) landed
        __syncthreads();

        if (i + 2 < NKVT) {        // refill K slot (K(i) dead since iter i-1)
            load_k((i + 2) * KVBLK, sb + FO_K + (uint32_t)((i & 1) * 32768));
            CP_COMMIT;
        }
        if (i + 1 < NKVT) qk_tile(i + 1, snext);   // tensor pipe works ahead

        // ==== softmax(i) on scur (overlaps QK(i+1) in the tensor pipe) ====
        float mx0 = -1e30f, mx1 = -1e30f;
        #pragma unroll
        for (int nt = 0; nt < 8; nt++) {
            scur[nt][0] *= 0.0625f; scur[nt][1] *= 0.0625f;
            scur[nt][2] *= 0.0625f; scur[nt][3] *= 0.0625f;
            mx0 = fmaxf(mx0, fmaxf(scur[nt][0], scur[nt][1]));
            mx1 = fmaxf(mx1, fmaxf(scur[nt][2], scur[nt][3]));
        }
        mx0 = fmaxf(mx0, __shfl_xor_sync(0xffffffffu, mx0, 1));
        mx0 = fmaxf(mx0, __shfl_xor_sync(0xffffffffu, mx0, 2));
        mx1 = fmaxf(mx1, __shfl_xor_sync(0xffffffffu, mx1, 1));
        mx1 = fmaxf(mx1, __shfl_xor_sync(0xffffffffu, mx1, 2));
        const float mn0 = fmaxf(m0, mx0), mn1 = fmaxf(m1, mx1);
        const float sc0 = __expf(m0 - mn0), sc1 = __expf(m1 - mn1);
        m0 = mn0; m1 = mn1;
        l0 *= sc0; l1 *= sc1;
        if (sc0 != 1.f || sc1 != 1.f) {
            #pragma unroll
            for (int nt = 0; nt < 32; nt++) {
                o[nt][0] *= sc0; o[nt][1] *= sc0;
                o[nt][2] *= sc1; o[nt][3] *= sc1;
            }
        }
        float rs0 = 0.f, rs1 = 0.f;
        #pragma unroll
        for (int nt = 0; nt < 8; nt++) {
            scur[nt][0] = __expf(scur[nt][0] - m0);
            scur[nt][1] = __expf(scur[nt][1] - m0);
            scur[nt][2] = __expf(scur[nt][2] - m1);
            scur[nt][3] = __expf(scur[nt][3] - m1);
            rs0 += scur[nt][0] + scur[nt][1];
            rs1 += scur[nt][2] + scur[nt][3];
        }
        rs0 += __shfl_xor_sync(0xffffffffu, rs0, 1);
        rs0 += __shfl_xor_sync(0xffffffffu, rs0, 2);
        rs1 += __shfl_xor_sync(0xffffffffu, rs1, 1);
        rs1 += __shfl_xor_sync(0xffffffffu, rs1, 2);
        l0 += rs0; l1 += rs1;

        uint32_t pah[4][4];
        #pragma unroll
        for (int ks = 0; ks < 4; ks++) {
            const int j0 = 2 * ks, j1 = 2 * ks + 1;
            pah[ks][0] = packh2(scur[j0][0], scur[j0][1]);
            pah[ks][1] = packh2(scur[j0][2], scur[j0][3]);
            pah[ks][2] = packh2(scur[j1][0], scur[j1][1]);
            pah[ks][3] = packh2(scur[j1][2], scur[j1][3]);
        }

        // ==== PV(i) ====
        const uint32_t vbs = sb + FO_V + (uint32_t)((i & 1) * 32768);
        #pragma unroll
        for (int j2 = 0; j2 < 16; j2++) {
            const int row = j2 * 16 + b_row;
            const uint32_t vrow = (uint32_t)(row * 128);
            const int r7 = row & 7;
            #pragma unroll
            for (int ks = 0; ks < 4; ks++) {
                uint32_t vh4[4];
                ldsm_x4(vh4, vbs + vrow + (uint32_t)((((2 * ks + b_kb) ^ r7) << 4)));
                mma16816(o[j2 * 2],     pah[ks], vh4[0], vh4[1]);
                mma16816(o[j2 * 2 + 1], pah[ks], vh4[2], vh4[3]);
            }
        }
        __syncthreads();

        if (i + 2 < NKVT) {        // refill V slot (V(i) free after PV + sync)
            load_v((i + 2) * KVBLK, sb + FO_V + (uint32_t)((i & 1) * 32768));
            CP_COMMIT;
        }
    };

    #pragma unroll 1
    for (int i = 0; i < NKVT; i += 2) {
        step(i,     sA, sB);
        step(i + 1, sB, sA);
    }

    const float inv0 = 1.f / l0, inv1 = 1.f / l1;
    const int g  = lane >> 2;
    const int t2 = (lane & 3) * 2;
    const size_t base0 = (size_t)(b * S_ + q0 + wm + g) * INNER_ + hd * 256 + t2;
    const size_t base1 = base0 + (size_t)8 * INNER_;
    #pragma unroll
    for (int nt = 0; nt < 32; nt++) {
        *(uint32_t*)&oh_g[base0 + (size_t)nt * 8] = packh2(o[nt][0] * inv0, o[nt][1] * inv0);
        *(uint32_t*)&oh_g[base1 + (size_t)nt * 8] = packh2(o[nt][2] * inv1, o[nt][3] * inv1);
    }
}

// ---------------- pure fp16 HMMA GEMM, KB=64, cp.async 2-stage, 2 CTA/SM ------
// C = alpha * A @ B^T
#define KB_    64
#define ASTR   144
#define GTILE  (128 * ASTR)       // 18432 B
#define G_SMEM (4 * GTILE)        // 73728 B

template<int OUT_HALF>
__global__ void __launch_bounds__(256, 2)
gemm_hmma1(const h16* __restrict__ Ah, int lda,
           const h16* __restrict__ Bh, int ldb,
           float* __restrict__ Cf, h16* __restrict__ Ch, int ldc,
           int K, int zdiv,
           long long sA1, long long sA2,
           long long sB1, long long sB2,
           long long sC1, long long sC2,
           const float* __restrict__ bias,
           float alpha, int relu)
{
    extern __shared__ __align__(16) char gsm[];
    const uint32_t uA = smem_u32(gsm);
    const uint32_t uB = uA + 2 * GTILE;

    const int z  = blockIdx.z;
    const int zq = z / zdiv, zr = z % zdiv;
    Ah += (long long)zq * sA1 + (long long)zr * sA2;
    Bh += (long long)zq * sB1 + (long long)zr * sB2;
    const long long coff = (long long)zq * sC1 + (long long)zr * sC2;
    if (Cf) Cf += coff;
    if (Ch) Ch += coff;

    const int bm   = blockIdx.y * 128;
    const int bn   = blockIdx.x * 128;
    const int tid  = threadIdx.x;
    const int wid  = tid >> 5;
    const int lane = tid & 31;
    const int wm   = (wid & 1) * 64;
    const int wn   = (wid >> 1) * 32;

    auto load_tile = [&](int kb, int buf) {
        const uint32_t off = (uint32_t)(buf * GTILE);
        #pragma unroll
        for (int it = 0; it < 4; it++) {
            int c = tid + it * 256;
            int row = c >> 3, kc = c & 7;
            const uint32_t so = (uint32_t)(row * ASTR + kc * 16);
            const int kn = kb * KB_ + kc * 8;
            CP16(uA + off + so, Ah + (long long)(bm + row) * lda + kn);
            CP16(uB + off + so, Bh + (long long)(bn + row) * ldb + kn);
        }
    };

    const uint32_t aBase = (uint32_t)((wm + (lane & 15)) * ASTR + (lane >> 4) * 16);
    const uint32_t bBase = (uint32_t)((wn + (lane & 7) + ((lane >> 4) & 1) * 8) * ASTR
                                      + (lane & 8) * 2);

    float acc[4][4][4];
    #pragma unroll
    for (int mt = 0; mt < 4; mt++)
        #pragma unroll
        for (int nt = 0; nt < 4; nt++)
            #pragma unroll
            for (int i = 0; i < 4; i++) acc[mt][nt][i] = 0.f;

    const int nkb = K / KB_;
    load_tile(0, 0); CP_COMMIT;
    load_tile(1, 1); CP_COMMIT;

    for (int kb = 0; kb < nkb; kb++) {
        if (kb + 1 < nkb) { CP_WAIT1; } else { CP_WAIT0; }
        __syncthreads();
        const uint32_t boff = (uint32_t)((kb & 1) * GTILE);

        #pragma unroll
        for (int ks = 0; ks < 4; ks++) {
            const uint32_t ksb = ks * 32;
            uint32_t ah[4][4];
            #pragma unroll
            for (int mt = 0; mt < 4; mt++)
                ldsm_x4(ah[mt], uA + boff + aBase + mt * (16 * ASTR) + ksb);
            uint32_t bh[2][4];
            #pragma unroll
            for (int g = 0; g < 2; g++)
                ldsm_x4(bh[g], uB + boff + bBase + g * (16 * ASTR) + ksb);
            #pragma unroll
            for (int mt = 0; mt < 4; mt++)
                #pragma unroll
                for (int nt = 0; nt < 4; nt++)
                    mma16816(acc[mt][nt], ah[mt],
                             bh[nt >> 1][(nt & 1) * 2], bh[nt >> 1][(nt & 1) * 2 + 1]);
        }
        __syncthreads();

        if (kb + 2 < nkb) { load_tile(kb + 2, kb & 1); CP_COMMIT; }
    }

    const int er = lane >> 2;
    const int ec = (lane & 3) * 2;
    #pragma unroll
    for (int mt = 0; mt < 4; mt++) {
        #pragma unroll
        for (int half = 0; half < 2; half++) {
            const int m = bm + wm + mt * 16 + er + half * 8;
            #pragma unroll
            for (int nt = 0; nt < 4; nt++) {
                const int n = bn + wn + nt * 8 + ec;
                float v0 = acc[mt][nt][half * 2 + 0] * alpha;
                float v1 = acc[mt][nt][half * 2 + 1] * alpha;
                if (bias) { v0 += __ldg(&bias[n]); v1 += __ldg(&bias[n + 1]); }
                if (relu) { v0 = fmaxf(v0, 0.f); v1 = fmaxf(v1, 0.f); }
                if (OUT_HALF) {
                    *(uint32_t*)&Ch[(long long)m * ldc + n] = packh2(v0, v1);
                } else {
                    *(float2*)&Cf[(long long)m * ldc + n] = make_float2(v0, v1);
                }
            }
        }
    }
}

// ---------------- warp-per-row split-K reduce + layernorm ----------------
__device__ __forceinline__ float warp_sum(float v) {
    #pragma unroll
    for (int o = 16; o > 0; o >>= 1) v += __shfl_xor_sync(0xffffffffu, v, o);
    return v;
}

__global__ void ln_red_kernel(const float* __restrict__ part, long long pstride,
                              const float* __restrict__ bias,
                              const float* __restrict__ resid,
                              const float* __restrict__ g,
                              const float* __restrict__ b,
                              float* __restrict__ outf,
                              h16* __restrict__ oh)
{
    const int lane = threadIdx.x & 31;
    const int warp = threadIdx.x >> 5;
    const long long row  = (long long)blockIdx.x * 8 + warp;
    const long long base = row * E_;

    float v[8];
    float sum = 0.f;
    #pragma unroll
    for (int j = 0; j < 8; j++) {
        const long long idx = base + lane + j * 32;
        float t = part[idx] + part[idx + pstride]
                + part[idx + 2 * pstride] + part[idx + 3 * pstride];
        if (bias) t += bias[lane + j * 32];
        t += resid[idx];
        v[j] = t;
        sum += t;
    }
    const float mean = warp_sum(sum) * (1.f / E_);
    float vs = 0.f;
    #pragma unroll
    for (int j = 0; j < 8; j++) {
        v[j] -= mean;
        vs += v[j] * v[j];
    }
    const float inv = rsqrtf(warp_sum(vs) * (1.f / E_) + EPS_);
    #pragma unroll
    for (int j = 0; j < 8; j++) {
        const int col = lane + j * 32;
        const float r = v[j] * inv * g[col] + b[col];
        if (outf) outf[base + col] = r;
        if (oh) oh[base + col] = __float2half_rn(r);
    }
}

// ---------------- prep kernels ----------------
__global__ void split_kernel(const float* __restrict__ in,
                             h16* __restrict__ oh, int n)
{
    int i = blockIdx.x * blockDim.x + threadIdx.x;
    if (i < n) oh[i] = __float2half_rn(in[i]);
}

__device__ __forceinline__ void wconv_tile(const float* W, int R, int C,
                                           h16* oh, int c0, int r0, int tx, int ty)
{
    __shared__ float t[32][33];
    #pragma unroll
    for (int j = 0; j < 4; j++) {
        int r = ty + 8 * j;
        t[r][tx] = W[(long long)(r0 + r) * C + c0 + tx];
    }
    __syncthreads();
    #pragma unroll
    for (int j = 0; j < 4; j++) {
        int r = ty + 8 * j;
        oh[(long long)(c0 + r) * R + r0 + tx] = __float2half_rn(t[tx][r]);
    }
}

__global__ void wconv_qkv(const float* __restrict__ Wq, const float* __restrict__ Wk,
                          const float* __restrict__ Wv, h16* __restrict__ oh)
{
    const float* W = (blockIdx.z == 0) ? Wq : (blockIdx.z == 1) ? Wk : Wv;
    h16* ph = oh + (size_t)blockIdx.z * INNER_ * E_;
    wconv_tile(W, E_, INNER_, ph, blockIdx.x * 32, blockIdx.y * 32,
               threadIdx.x, threadIdx.y);
}

__global__ void wconv_misc(const float* __restrict__ Wo, const float* __restrict__ W1,
                           const float* __restrict__ W2,
                           h16* __restrict__ woT, h16* __restrict__ w1T,
                           h16* __restrict__ w2T)
{
    const float* W; h16* ph; int R, C;
    if (blockIdx.z == 0)      { W = Wo; ph = woT; R = INNER_; C = E_; }
    else if (blockIdx.z == 1) { W = W1; ph = w1T; R = E_; C = DFF_; }
    else                      { W = W2; ph = w2T; R = DFF_; C = E_; }
    if ((int)blockIdx.x * 32 >= C || (int)blockIdx.y * 32 >= R) return;
    wconv_tile(W, R, C, ph, blockIdx.x * 32, blockIdx.y * 32,
               threadIdx.x, threadIdx.y);
}

__global__ void vtrans_kernel(const h16* __restrict__ qkvh,
                              h16* __restrict__ vth)
{
    __shared__ h16 th[32][33];
    const int z = blockIdx.z;
    const int b = z / H_, h = z % H_;
    const int s0 = blockIdx.x * 32;
    const int d0 = blockIdx.y * 32;
    const int tx = threadIdx.x, ty = threadIdx.y;
    const long long ibase = (long long)b * S_ * QKVW_ + 4096 + (long long)h * DH_;
    const long long obase = (long long)z * DH_ * S_;
    #pragma unroll
    for (int j = 0; j < 4; j++) {
        int r = ty + 8 * j;
        th[r][tx] = qkvh[ibase + (long long)(s0 + r) * QKVW_ + d0 + tx];
    }
    __syncthreads();
    #pragma unroll
    for (int j = 0; j < 4; j++) {
        int r = ty + 8 * j;
        vth[obase + (long long)(d0 + r) * S_ + s0 + tx] = th[tx][r];
    }
}

// ---------------- launch ----------------
extern "C" void kernel_launch(void* const* d_in, const int* in_sizes, int n_in,
                              void* d_out, int out_size)
{
    const float* x    = (const float*)d_in[0];
    const float* Wq   = (const float*)d_in[1];
    const float* Wk   = (const float*)d_in[2];
    const float* Wv   = (const float*)d_in[3];
    const float* Wo   = (const float*)d_in[4];
    const float* W1   = (const float*)d_in[5];
    const float* b1   = (const float*)d_in[6];
    const float* W2   = (const float*)d_in[7];
    const float* b2   = (const float*)d_in[8];
    const float* ln1g = (const float*)d_in[9];
    const float* ln1b = (const float*)d_in[10];
    const float* ln2g = (const float*)d_in[11];
    const float* ln2b = (const float*)d_in[12];

    #define SYM(p, s) p; cudaGetSymbolAddress((void**)&p, s)
    h16 *SYM(xh, g_xh);
    h16 *SYM(wqkv, g_wqkvT);
    h16 *SYM(woT, g_woT);
    h16 *SYM(w1T, g_w1T);
    h16 *SYM(w2T, g_w2T);
    h16 *SYM(qkvh, g_qkvh);
    h16 *SYM(vth, g_vth);
    h16 *SYM(oh, g_oh);
    float *SYM(part, g_part);
    float *SYM(hf, g_hf);
    h16 *SYM(hh, g_hh);
    h16 *SYM(ffh, g_ffh);

    cudaFuncSetAttribute(flash_kernel, cudaFuncAttributeMaxDynamicSharedMemorySize, F_SMEM);
    cudaFuncSetAttribute(gemm_hmma1<0>, cudaFuncAttributeMaxDynamicSharedMemorySize, G_SMEM);
    cudaFuncSetAttribute(gemm_hmma1<1>, cudaFuncAttributeMaxDynamicSharedMemorySize, G_SMEM);

    const dim3 blk(256);
    const dim3 tblk(32, 8);
    const long long psz = (long long)BSZ * E_;

    // 1) x -> fp16
    split_kernel<<<(BSZ * E_ + 255) / 256, 256>>>(x, xh, BSZ * E_);
    // 2) QKV weights packed convert-transpose
    { dim3 g(INNER_/32, E_/32, 3); wconv_qkv<<<g, tblk>>>(Wq, Wk, Wv, wqkv); }
    // 3) Wo/W1/W2
    { dim3 g(64, 64, 3); wconv_misc<<<g, tblk>>>(Wo, W1, W2, woT, w1T, w2T); }
    // 4) fused QKV projection: [4096,256] @ [256,6144]
    {
        dim3 grd(QKVW_/128, BSZ/128, 1);
        gemm_hmma1<1><<<grd, blk, G_SMEM>>>(xh, E_, wqkv, E_,
            nullptr, qkvh, QKVW_, E_, 1, 0,0, 0,0, 0,0,
            nullptr, 1.f, 0);
    }
    // 5) V^T per (b,h)
    { dim3 g(S_/32, DH_/32, B_*H_); vtrans_kernel<<<g, tblk>>>(qkvh, vth); }
    // 6) flash attention (ping-pong)
    {
        dim3 grd(S_/QBLK, B_*H_);
        flash_kernel<<<grd, blk, F_SMEM>>>(qkvh, vth, oh);
    }
    // 7) Wo split-K x4 -> partials ; LN1 reduce (+x resid)
    {
        dim3 grd(E_/128, BSZ/128, 4);
        gemm_hmma1<0><<<grd, blk, G_SMEM>>>(oh, INNER_, woT, INNER_,
            part, nullptr, E_, INNER_/4, 4,
            0, 512, 0, 512, 0, psz,
            nullptr, 1.f, 0);
        ln_red_kernel<<<BSZ/8, 256>>>(part, psz, nullptr, x, ln1g, ln1b, hf, hh);
    }
    // 8) ff = relu(h @ W1 + b1)
    {
        dim3 grd(DFF_/128, BSZ/128, 1);
        gemm_hmma1<1><<<grd, blk, G_SMEM>>>(hh, E_, w1T, E_,
            nullptr, ffh, DFF_, E_, 1, 0,0, 0,0, 0,0,
            b1, 1.f, 1);
    }
    // 9) FFN2 split-K x4 -> partials ; LN2 reduce (+b2 +h resid) -> out
    {
        dim3 grd(E_/128, BSZ/128, 4);
        gemm_hmma1<0><<<grd, blk, G_SMEM>>>(ffh, DFF_, w2T, DFF_,
            part, nullptr, E_, DFF_/4, 4,
            0, 256, 0, 256, 0, psz,
            nullptr, 1.f, 0);
        ln_red_kernel<<<BSZ/8, 256>>>(part, psz, b2, hf, ln2g, ln2b,
                                      (float*)d_out, nullptr);
    }
}

// round 15
// speedup vs baseline: 1.1156x; 1.1156x over previous
#include <cuda_runtime.h>
#include <cuda_fp16.h>
#include <cstdint>

#define B_     2
#define S_     2048
#define E_     256
#define H_     8
#define DH_    256
#define INNER_ 2048
#define QKVW_  (3*INNER_)   // 6144
#define DFF_   1024
#define BSZ    (B_*S_)
#define EPS_   1e-6f

typedef __half h16;

// ---------------- device scratch ----------------
__device__ h16   g_xh [(size_t)BSZ * E_];
__device__ h16   g_wqkvT[(size_t)QKVW_ * E_];
__device__ h16   g_woT [(size_t)E_ * INNER_];
__device__ h16   g_w1T [(size_t)DFF_ * E_];
__device__ h16   g_w2T [(size_t)E_ * DFF_];
__device__ h16   g_qkvh[(size_t)BSZ * QKVW_];     // q|k|v packed, ld=6144
__device__ h16   g_vth[(size_t)BSZ * INNER_];     // V^T per (b,h): [B*H][DH][S]
__device__ h16   g_oh [(size_t)BSZ * INNER_];
__device__ float g_part[(size_t)4 * BSZ * E_];    // split-K partials
__device__ float g_hf [(size_t)BSZ * E_];
__device__ h16   g_hh [(size_t)BSZ * E_];
__device__ h16   g_ffh[(size_t)BSZ * DFF_];

// ---------------- helpers ----------------
__device__ __forceinline__ uint32_t smem_u32(const void* p) {
    uint32_t a;
    asm("{ .reg .u64 t; cvta.to.shared.u64 t, %1; cvt.u32.u64 %0, t; }"
        : "=r"(a) : "l"(p));
    return a;
}
__device__ __forceinline__ void ldsm_x4(uint32_t* r, uint32_t a) {
    asm volatile("ldmatrix.sync.aligned.m8n8.x4.shared.b16 {%0,%1,%2,%3}, [%4];"
                 : "=r"(r[0]), "=r"(r[1]), "=r"(r[2]), "=r"(r[3]) : "r"(a));
}
__device__ __forceinline__ void mma16816(float* c, const uint32_t* a,
                                         uint32_t b0, uint32_t b1) {
    asm volatile(
        "mma.sync.aligned.m16n8k16.row.col.f32.f16.f16.f32 "
        "{%0,%1,%2,%3}, {%4,%5,%6,%7}, {%8,%9}, {%0,%1,%2,%3};"
        : "+f"(c[0]), "+f"(c[1]), "+f"(c[2]), "+f"(c[3])
        : "r"(a[0]), "r"(a[1]), "r"(a[2]), "r"(a[3]), "r"(b0), "r"(b1));
}
#define CP16(dst, src) \
    asm volatile("cp.async.cg.shared.global [%0], [%1], 16;" :: "r"(dst), "l"(src) : "memory")
#define CP_COMMIT  asm volatile("cp.async.commit_group;" ::: "memory")
#define CP_WAIT0   asm volatile("cp.async.wait_group 0;" ::: "memory")
#define CP_WAIT1   asm volatile("cp.async.wait_group 1;" ::: "memory")

__device__ __forceinline__ uint32_t packh2(float x, float y) {
    __half2 t = __floats2half2_rn(x, y);
    return *(uint32_t*)&t;
}

// ================= flash attention, KVBLK=64 (round-13 verified) =============
// grid (S_/128, B_*H_), 256 thr (8 warps x m16). Q resident (64KB),
// K + V double-buffered at 32KB slots, one cp.async group per iter.
#define QBLK   128
#define KVBLK  64
#define NKVT   (S_/KVBLK)      // 32
#define FO_K   65536           // 2 slots x 32768
#define FO_V   131072          // 2 slots x 32768
#define F_SMEM 196608

__global__ void __launch_bounds__(256)
flash_kernel(const h16* __restrict__ qkvh,
             const h16* __restrict__ vth_g,
             h16* __restrict__ oh_g)
{
    extern __shared__ __align__(128) char sm[];
    const uint32_t sb = smem_u32(sm);
    const int tid = threadIdx.x, wid = tid >> 5, lane = tid & 31;
    const int bh = blockIdx.y;
    const int b = bh >> 3, hd = bh & 7;
    const int q0 = blockIdx.x * QBLK;

    auto load_k = [&](int kv0, uint32_t slot) {      // 64 rows x 512B
        #pragma unroll
        for (int it = 0; it < 8; it++) {
            int c = tid + it * 256;
            int row = c >> 5, kc = c & 31;
            const h16* src = qkvh
                + ((size_t)(b * S_ + kv0 + row) * QKVW_ + 2048 + hd * 256 + kc * 8);
            CP16(slot + row * 512 + (uint32_t)((kc ^ (row & 7)) << 4), src);
        }
    };
    auto load_v = [&](int kv0, uint32_t slot) {      // 256 rows x 128B
        #pragma unroll
        for (int it = 0; it < 8; it++) {
            int c = tid + it * 256;
            int row = c >> 3, kc = c & 7;
            const h16* src = vth_g
                + ((size_t)bh * DH_ * S_ + (size_t)row * S_ + kv0 + kc * 8);
            CP16(slot + row * 128 + (uint32_t)((kc ^ (row & 7)) << 4), src);
        }
    };

    #pragma unroll
    for (int it = 0; it < 16; it++) {                 // Q: 128 rows x 512B
        int c = tid + it * 256;
        int row = c >> 5, kc = c & 31;
        const h16* src = qkvh
            + ((size_t)(b * S_ + q0 + row) * QKVW_ + hd * 256 + kc * 8);
        CP16(sb + row * 512 + (uint32_t)((kc ^ (row & 7)) << 4), src);
    }
    load_k(0, sb + FO_K);
    load_v(0, sb + FO_V);
    CP_COMMIT;
    load_k(KVBLK, sb + FO_K + 32768);
    load_v(KVBLK, sb + FO_V + 32768);
    CP_COMMIT;

    const int wm    = wid * 16;
    const int a_row = wm + (lane & 15);
    const uint32_t a_rowoff = (uint32_t)(a_row * 512);
    const int a_r7  = a_row & 7;
    const int a_hb  = lane >> 4;
    const int b_row = (lane & 7) + ((lane >> 4) & 1) * 8;
    const int b_kb  = (lane >> 3) & 1;

    float o[32][4];
    #pragma unroll
    for (int i = 0; i < 32; i++) { o[i][0]=0.f; o[i][1]=0.f; o[i][2]=0.f; o[i][3]=0.f; }
    float m0 = -1e30f, m1 = -1e30f, l0 = 0.f, l1 = 0.f;

    for (int i = 0; i < NKVT; i++) {
        if (i + 1 < NKVT) { CP_WAIT1; } else { CP_WAIT0; }   // K(i),V(i) ready
        __syncthreads();
        const uint32_t kbs = sb + FO_K + (uint32_t)((i & 1) * 32768);
        const uint32_t vbs = sb + FO_V + (uint32_t)((i & 1) * 32768);

        // ==== S[16 x 64] = Qh Kh^T ====
        float s[8][4];
        #pragma unroll
        for (int nt = 0; nt < 8; nt++) { s[nt][0]=0.f; s[nt][1]=0.f; s[nt][2]=0.f; s[nt][3]=0.f; }
        #pragma unroll
        for (int ks = 0; ks < 16; ks++) {
            const uint32_t aq = a_rowoff + (uint32_t)((((2 * ks + a_hb) ^ a_r7) << 4));
            uint32_t ah4[4];
            ldsm_x4(ah4, sb + aq);
            uint32_t kh4[4][4];
            #pragma unroll
            for (int g2 = 0; g2 < 4; g2++) {
                const int row = g2 * 16 + b_row;
                const uint32_t off = (uint32_t)(row * 512 + (((2 * ks + b_kb) ^ (row & 7)) << 4));
                ldsm_x4(kh4[g2], kbs + off);
            }
            #pragma unroll
            for (int nt = 0; nt < 8; nt++)
                mma16816(s[nt], ah4, kh4[nt >> 1][(nt & 1) * 2], kh4[nt >> 1][(nt & 1) * 2 + 1]);
        }

        // ==== online softmax (rows g=lane>>2, g+8) ====
        float mx0 = -1e30f, mx1 = -1e30f;
        #pragma unroll
        for (int nt = 0; nt < 8; nt++) {
            s[nt][0] *= 0.0625f; s[nt][1] *= 0.0625f;
            s[nt][2] *= 0.0625f; s[nt][3] *= 0.0625f;
            mx0 = fmaxf(mx0, fmaxf(s[nt][0], s[nt][1]));
            mx1 = fmaxf(mx1, fmaxf(s[nt][2], s[nt][3]));
        }
        mx0 = fmaxf(mx0, __shfl_xor_sync(0xffffffffu, mx0, 1));
        mx0 = fmaxf(mx0, __shfl_xor_sync(0xffffffffu, mx0, 2));
        mx1 = fmaxf(mx1, __shfl_xor_sync(0xffffffffu, mx1, 1));
        mx1 = fmaxf(mx1, __shfl_xor_sync(0xffffffffu, mx1, 2));
        const float mn0 = fmaxf(m0, mx0), mn1 = fmaxf(m1, mx1);
        const float sc0 = __expf(m0 - mn0), sc1 = __expf(m1 - mn1);
        m0 = mn0; m1 = mn1;
        l0 *= sc0; l1 *= sc1;
        if (sc0 != 1.f || sc1 != 1.f) {
            #pragma unroll
            for (int nt = 0; nt < 32; nt++) {
                o[nt][0] *= sc0; o[nt][1] *= sc0;
                o[nt][2] *= sc1; o[nt][3] *= sc1;
            }
        }
        float rs0 = 0.f, rs1 = 0.f;
        #pragma unroll
        for (int nt = 0; nt < 8; nt++) {
            s[nt][0] = __expf(s[nt][0] - m0);
            s[nt][1] = __expf(s[nt][1] - m0);
            s[nt][2] = __expf(s[nt][2] - m1);
            s[nt][3] = __expf(s[nt][3] - m1);
            rs0 += s[nt][0] + s[nt][1];
            rs1 += s[nt][2] + s[nt][3];
        }
        rs0 += __shfl_xor_sync(0xffffffffu, rs0, 1);
        rs0 += __shfl_xor_sync(0xffffffffu, rs0, 2);
        rs1 += __shfl_xor_sync(0xffffffffu, rs1, 1);
        rs1 += __shfl_xor_sync(0xffffffffu, rs1, 2);
        l0 += rs0; l1 += rs1;

        // P -> fp16 A-fragments (k64 = 4 k16 steps)
        uint32_t pah[4][4];
        #pragma unroll
        for (int ks = 0; ks < 4; ks++) {
            const int j0 = 2 * ks, j1 = 2 * ks + 1;
            pah[ks][0] = packh2(s[j0][0], s[j0][1]);
            pah[ks][1] = packh2(s[j0][2], s[j0][3]);
            pah[ks][2] = packh2(s[j1][0], s[j1][1]);
            pah[ks][3] = packh2(s[j1][2], s[j1][3]);
        }

        // ==== O += P @ Vh over dh=256 ====
        #pragma unroll
        for (int j2 = 0; j2 < 16; j2++) {
            const int row = j2 * 16 + b_row;
            const uint32_t vrow = (uint32_t)(row * 128);
            const int r7 = row & 7;
            #pragma unroll
            for (int ks = 0; ks < 4; ks++) {
                uint32_t vh4[4];
                ldsm_x4(vh4, vbs + vrow + (uint32_t)((((2 * ks + b_kb) ^ r7) << 4)));
                mma16816(o[j2 * 2],     pah[ks], vh4[0], vh4[1]);
                mma16816(o[j2 * 2 + 1], pah[ks], vh4[2], vh4[3]);
            }
        }
        __syncthreads();

        if (i + 2 < NKVT) {
            load_k((i + 2) * KVBLK, sb + FO_K + (uint32_t)((i & 1) * 32768));
            load_v((i + 2) * KVBLK, sb + FO_V + (uint32_t)((i & 1) * 32768));
            CP_COMMIT;
        }
    }

    const float inv0 = 1.f / l0, inv1 = 1.f / l1;
    const int g  = lane >> 2;
    const int t2 = (lane & 3) * 2;
    const size_t base0 = (size_t)(b * S_ + q0 + wm + g) * INNER_ + hd * 256 + t2;
    const size_t base1 = base0 + (size_t)8 * INNER_;
    #pragma unroll
    for (int nt = 0; nt < 32; nt++) {
        *(uint32_t*)&oh_g[base0 + (size_t)nt * 8] = packh2(o[nt][0] * inv0, o[nt][1] * inv0);
        *(uint32_t*)&oh_g[base1 + (size_t)nt * 8] = packh2(o[nt][2] * inv1, o[nt][3] * inv1);
    }
}

// ---------------- pure fp16 HMMA GEMM, KB=64, cp.async 2-stage, 2 CTA/SM ------
// C = alpha * A @ B^T
#define KB_    64
#define ASTR   144
#define GTILE  (128 * ASTR)       // 18432 B
#define G_SMEM (4 * GTILE)        // 73728 B

template<int OUT_HALF>
__global__ void __launch_bounds__(256, 2)
gemm_hmma1(const h16* __restrict__ Ah, int lda,
           const h16* __restrict__ Bh, int ldb,
           float* __restrict__ Cf, h16* __restrict__ Ch, int ldc,
           int K, int zdiv,
           long long sA1, long long sA2,
           long long sB1, long long sB2,
           long long sC1, long long sC2,
           const float* __restrict__ bias,
           float alpha, int relu)
{
    extern __shared__ __align__(16) char gsm[];
    const uint32_t uA = smem_u32(gsm);
    const uint32_t uB = uA + 2 * GTILE;

    const int z  = blockIdx.z;
    const int zq = z / zdiv, zr = z % zdiv;
    Ah += (long long)zq * sA1 + (long long)zr * sA2;
    Bh += (long long)zq * sB1 + (long long)zr * sB2;
    const long long coff = (long long)zq * sC1 + (long long)zr * sC2;
    if (Cf) Cf += coff;
    if (Ch) Ch += coff;

    const int bm   = blockIdx.y * 128;
    const int bn   = blockIdx.x * 128;
    const int tid  = threadIdx.x;
    const int wid  = tid >> 5;
    const int lane = tid & 31;
    const int wm   = (wid & 1) * 64;
    const int wn   = (wid >> 1) * 32;

    auto load_tile = [&](int kb, int buf) {
        const uint32_t off = (uint32_t)(buf * GTILE);
        #pragma unroll
        for (int it = 0; it < 4; it++) {
            int c = tid + it * 256;
            int row = c >> 3, kc = c & 7;
            const uint32_t so = (uint32_t)(row * ASTR + kc * 16);
            const int kn = kb * KB_ + kc * 8;
            CP16(uA + off + so, Ah + (long long)(bm + row) * lda + kn);
            CP16(uB + off + so, Bh + (long long)(bn + row) * ldb + kn);
        }
    };

    const uint32_t aBase = (uint32_t)((wm + (lane & 15)) * ASTR + (lane >> 4) * 16);
    const uint32_t bBase = (uint32_t)((wn + (lane & 7) + ((lane >> 4) & 1) * 8) * ASTR
                                      + (lane & 8) * 2);

    float acc[4][4][4];
    #pragma unroll
    for (int mt = 0; mt < 4; mt++)
        #pragma unroll
        for (int nt = 0; nt < 4; nt++)
            #pragma unroll
            for (int i = 0; i < 4; i++) acc[mt][nt][i] = 0.f;

    const int nkb = K / KB_;
    load_tile(0, 0); CP_COMMIT;
    load_tile(1, 1); CP_COMMIT;

    for (int kb = 0; kb < nkb; kb++) {
        if (kb + 1 < nkb) { CP_WAIT1; } else { CP_WAIT0; }
        __syncthreads();
        const uint32_t boff = (uint32_t)((kb & 1) * GTILE);

        #pragma unroll
        for (int ks = 0; ks < 4; ks++) {
            const uint32_t ksb = ks * 32;
            uint32_t ah[4][4];
            #pragma unroll
            for (int mt = 0; mt < 4; mt++)
                ldsm_x4(ah[mt], uA + boff + aBase + mt * (16 * ASTR) + ksb);
            uint32_t bh[2][4];
            #pragma unroll
            for (int g = 0; g < 2; g++)
                ldsm_x4(bh[g], uB + boff + bBase + g * (16 * ASTR) + ksb);
            #pragma unroll
            for (int mt = 0; mt < 4; mt++)
                #pragma unroll
                for (int nt = 0; nt < 4; nt++)
                    mma16816(acc[mt][nt], ah[mt],
                             bh[nt >> 1][(nt & 1) * 2], bh[nt >> 1][(nt & 1) * 2 + 1]);
        }
        __syncthreads();

        if (kb + 2 < nkb) { load_tile(kb + 2, kb & 1); CP_COMMIT; }
    }

    const int er = lane >> 2;
    const int ec = (lane & 3) * 2;
    #pragma unroll
    for (int mt = 0; mt < 4; mt++) {
        #pragma unroll
        for (int half = 0; half < 2; half++) {
            const int m = bm + wm + mt * 16 + er + half * 8;
            #pragma unroll
            for (int nt = 0; nt < 4; nt++) {
                const int n = bn + wn + nt * 8 + ec;
                float v0 = acc[mt][nt][half * 2 + 0] * alpha;
                float v1 = acc[mt][nt][half * 2 + 1] * alpha;
                if (bias) { v0 += __ldg(&bias[n]); v1 += __ldg(&bias[n + 1]); }
                if (relu) { v0 = fmaxf(v0, 0.f); v1 = fmaxf(v1, 0.f); }
                if (OUT_HALF) {
                    *(uint32_t*)&Ch[(long long)m * ldc + n] = packh2(v0, v1);
                } else {
                    *(float2*)&Cf[(long long)m * ldc + n] = make_float2(v0, v1);
                }
            }
        }
    }
}

// ---------------- warp-per-row split-K reduce + layernorm ----------------
__device__ __forceinline__ float warp_sum(float v) {
    #pragma unroll
    for (int o = 16; o > 0; o >>= 1) v += __shfl_xor_sync(0xffffffffu, v, o);
    return v;
}

__global__ void ln_red_kernel(const float* __restrict__ part, long long pstride,
                              const float* __restrict__ bias,
                              const float* __restrict__ resid,
                              const float* __restrict__ g,
                              const float* __restrict__ b,
                              float* __restrict__ outf,
                              h16* __restrict__ oh)
{
    const int lane = threadIdx.x & 31;
    const int warp = threadIdx.x >> 5;
    const long long row  = (long long)blockIdx.x * 8 + warp;
    const long long base = row * E_;

    float v[8];
    float sum = 0.f;
    #pragma unroll
    for (int j = 0; j < 8; j++) {
        const long long idx = base + lane + j * 32;
        float t = part[idx] + part[idx + pstride]
                + part[idx + 2 * pstride] + part[idx + 3 * pstride];
        if (bias) t += bias[lane + j * 32];
        t += resid[idx];
        v[j] = t;
        sum += t;
    }
    const float mean = warp_sum(sum) * (1.f / E_);
    float vs = 0.f;
    #pragma unroll
    for (int j = 0; j < 8; j++) {
        v[j] -= mean;
        vs += v[j] * v[j];
    }
    const float inv = rsqrtf(warp_sum(vs) * (1.f / E_) + EPS_);
    #pragma unroll
    for (int j = 0; j < 8; j++) {
        const int col = lane + j * 32;
        const float r = v[j] * inv * g[col] + b[col];
        if (outf) outf[base + col] = r;
        if (oh) oh[base + col] = __float2half_rn(r);
    }
}

// ---------------- unified prep: weights + x convert, one launch ----------------
__device__ __forceinline__ void wconv_tile(const float* W, int R, int C,
                                           h16* oh, int c0, int r0, int tx, int ty)
{
    __shared__ float t[32][33];
    #pragma unroll
    for (int j = 0; j < 4; j++) {
        int r = ty + 8 * j;
        t[r][tx] = W[(long long)(r0 + r) * C + c0 + tx];
    }
    __syncthreads();
    #pragma unroll
    for (int j = 0; j < 4; j++) {
        int r = ty + 8 * j;
        oh[(long long)(c0 + r) * R + r0 + tx] = __float2half_rn(t[tx][r]);
    }
}

// grid (64, 64, 7), block (32, 8).
// z 0..2: Wq/Wk/Wv -> packed wqkvT   (C=2048, R=256 -> x<64, y<8)
// z 3   : Wo -> woT                  (C=256,  R=2048 -> x<8,  y<64)
// z 4   : W1 -> w1T                  (C=1024, R=256  -> x<32, y<8)
// z 5   : W2 -> w2T                  (C=256,  R=1024 -> x<8,  y<32)
// z 6   : x fp32 -> fp16             (1M elems; 4096 blocks x 256)
__global__ void prep_kernel(const float* __restrict__ x,
                            const float* __restrict__ Wq, const float* __restrict__ Wk,
                            const float* __restrict__ Wv, const float* __restrict__ Wo,
                            const float* __restrict__ W1, const float* __restrict__ W2,
                            h16* __restrict__ xh, h16* __restrict__ wqkvT,
                            h16* __restrict__ woT, h16* __restrict__ w1T,
                            h16* __restrict__ w2T)
{
    const int zi = blockIdx.z;
    const int tx = threadIdx.x, ty = threadIdx.y;
    if (zi == 6) {
        const int i = (int)((blockIdx.y * 64 + blockIdx.x) * 256 + ty * 32 + tx);
        if (i < BSZ * E_) xh[i] = __float2half_rn(x[i]);
        return;
    }
    const float* W; h16* ph; int R, C;
    if (zi < 3) {
        W = (zi == 0) ? Wq : (zi == 1) ? Wk : Wv;
        ph = wqkvT + (size_t)zi * INNER_ * E_;
        R = E_; C = INNER_;
    } else if (zi == 3) { W = Wo; ph = woT; R = INNER_; C = E_; }
    else if (zi == 4)   { W = W1; ph = w1T; R = E_; C = DFF_; }
    else                { W = W2; ph = w2T; R = DFF_; C = E_; }
    if ((int)blockIdx.x * 32 >= C || (int)blockIdx.y * 32 >= R) return;
    wconv_tile(W, R, C, ph, blockIdx.x * 32, blockIdx.y * 32, tx, ty);
}

__global__ void vtrans_kernel(const h16* __restrict__ qkvh,
                              h16* __restrict__ vth)
{
    __shared__ h16 th[32][33];
    const int z = blockIdx.z;
    const int b = z / H_, h = z % H_;
    const int s0 = blockIdx.x * 32;
    const int d0 = blockIdx.y * 32;
    const int tx = threadIdx.x, ty = threadIdx.y;
    const long long ibase = (long long)b * S_ * QKVW_ + 4096 + (long long)h * DH_;
    const long long obase = (long long)z * DH_ * S_;
    #pragma unroll
    for (int j = 0; j < 4; j++) {
        int r = ty + 8 * j;
        th[r][tx] = qkvh[ibase + (long long)(s0 + r) * QKVW_ + d0 + tx];
    }
    __syncthreads();
    #pragma unroll
    for (int j = 0; j < 4; j++) {
        int r = ty + 8 * j;
        vth[obase + (long long)(d0 + r) * S_ + s0 + tx] = th[tx][r];
    }
}

// ---------------- launch ----------------
extern "C" void kernel_launch(void* const* d_in, const int* in_sizes, int n_in,
                              void* d_out, int out_size)
{
    const float* x    = (const float*)d_in[0];
    const float* Wq   = (const float*)d_in[1];
    const float* Wk   = (const float*)d_in[2];
    const float* Wv   = (const float*)d_in[3];
    const float* Wo   = (const float*)d_in[4];
    const float* W1   = (const float*)d_in[5];
    const float* b1   = (const float*)d_in[6];
    const float* W2   = (const float*)d_in[7];
    const float* b2   = (const float*)d_in[8];
    const float* ln1g = (const float*)d_in[9];
    const float* ln1b = (const float*)d_in[10];
    const float* ln2g = (const float*)d_in[11];
    const float* ln2b = (const float*)d_in[12];

    #define SYM(p, s) p; cudaGetSymbolAddress((void**)&p, s)
    h16 *SYM(xh, g_xh);
    h16 *SYM(wqkv, g_wqkvT);
    h16 *SYM(woT, g_woT);
    h16 *SYM(w1T, g_w1T);
    h16 *SYM(w2T, g_w2T);
    h16 *SYM(qkvh, g_qkvh);
    h16 *SYM(vth, g_vth);
    h16 *SYM(oh, g_oh);
    float *SYM(part, g_part);
    float *SYM(hf, g_hf);
    h16 *SYM(hh, g_hh);
    h16 *SYM(ffh, g_ffh);

    cudaFuncSetAttribute(flash_kernel, cudaFuncAttributeMaxDynamicSharedMemorySize, F_SMEM);
    cudaFuncSetAttribute(gemm_hmma1<0>, cudaFuncAttributeMaxDynamicSharedMemorySize, G_SMEM);
    cudaFuncSetAttribute(gemm_hmma1<1>, cudaFuncAttributeMaxDynamicSharedMemorySize, G_SMEM);

    const dim3 blk(256);
    const dim3 tblk(32, 8);
    const long long psz = (long long)BSZ * E_;

    // 1) unified prep: all weight converts + x convert
    { dim3 g(64, 64, 7); prep_kernel<<<g, tblk>>>(x, Wq, Wk, Wv, Wo, W1, W2,
                                                  xh, wqkv, woT, w1T, w2T); }
    // 2) fused QKV projection: [4096,256] @ [256,6144]
    {
        dim3 grd(QKVW_/128, BSZ/128, 1);
        gemm_hmma1<1><<<grd, blk, G_SMEM>>>(xh, E_, wqkv, E_,
            nullptr, qkvh, QKVW_, E_, 1, 0,0, 0,0, 0,0,
            nullptr, 1.f, 0);
    }
    // 3) V^T per (b,h)
    { dim3 g(S_/32, DH_/32, B_*H_); vtrans_kernel<<<g, tblk>>>(qkvh, vth); }
    // 4) flash attention
    {
        dim3 grd(S_/QBLK, B_*H_);
        flash_kernel<<<grd, blk, F_SMEM>>>(qkvh, vth, oh);
    }
    // 5) Wo split-K x4 -> partials ; LN1 reduce (+x resid)
    {
        dim3 grd(E_/128, BSZ/128, 4);
        gemm_hmma1<0><<<grd, blk, G_SMEM>>>(oh, INNER_, woT, INNER_,
            part, nullptr, E_, INNER_/4, 4,
            0, 512, 0, 512, 0, psz,
            nullptr, 1.f, 0);
        ln_red_kernel<<<BSZ/8, 256>>>(part, psz, nullptr, x, ln1g, ln1b, hf, hh);
    }
    // 6) ff = relu(h @ W1 + b1)
    {
        dim3 grd(DFF_/128, BSZ/128, 1);
        gemm_hmma1<1><<<grd, blk, G_SMEM>>>(hh, E_, w1T, E_,
            nullptr, ffh, DFF_, E_, 1, 0,0, 0,0, 0,0,
            b1, 1.f, 1);
    }
    // 7) FFN2 split-K x4 -> partials ; LN2 reduce (+b2 +h resid) -> out
    {
        dim3 grd(E_/128, BSZ/128, 4);
        gemm_hmma1<0><<<grd, blk, G_SMEM>>>(ffh, DFF_, w2T, DFF_,
            part, nullptr, E_, DFF_/4, 4,
            0, 256, 0, 256, 0, psz,
            nullptr, 1.f, 0);
        ln_red_kernel<<<BSZ/8, 256>>>(part, psz, b2, hf, ln2g, ln2b,
                                      (float*)d_out, nullptr);
    }
}

// round 16
// speedup vs baseline: 1.1295x; 1.0124x over previous
#include <cuda_runtime.h>
#include <cuda_fp16.h>
#include <cstdint>

#define B_     2
#define S_     2048
#define E_     256
#define H_     8
#define DH_    256
#define INNER_ 2048
#define QKVW_  (3*INNER_)   // 6144
#define DFF_   1024
#define BSZ    (B_*S_)
#define EPS_   1e-6f

typedef __half h16;

// ---------------- device scratch ----------------
__device__ h16   g_xh [(size_t)BSZ * E_];
__device__ h16   g_wqkvT[(size_t)QKVW_ * E_];
__device__ h16   g_woT [(size_t)E_ * INNER_];
__device__ h16   g_w1T [(size_t)DFF_ * E_];
__device__ h16   g_w2T [(size_t)E_ * DFF_];
__device__ h16   g_qkvh[(size_t)BSZ * QKVW_];     // q|k|v packed, ld=6144
__device__ h16   g_vth[(size_t)BSZ * INNER_];     // V^T per (b,h): [B*H][DH][S]
__device__ h16   g_oh [(size_t)BSZ * INNER_];
__device__ float g_part[(size_t)4 * BSZ * E_];    // split-K partials
__device__ float g_hf [(size_t)BSZ * E_];
__device__ h16   g_hh [(size_t)BSZ * E_];
__device__ h16   g_ffh[(size_t)BSZ * DFF_];

// ---------------- helpers ----------------
__device__ __forceinline__ uint32_t smem_u32(const void* p) {
    uint32_t a;
    asm("{ .reg .u64 t; cvta.to.shared.u64 t, %1; cvt.u32.u64 %0, t; }"
        : "=r"(a) : "l"(p));
    return a;
}
__device__ __forceinline__ void ldsm_x4(uint32_t* r, uint32_t a) {
    asm volatile("ldmatrix.sync.aligned.m8n8.x4.shared.b16 {%0,%1,%2,%3}, [%4];"
                 : "=r"(r[0]), "=r"(r[1]), "=r"(r[2]), "=r"(r[3]) : "r"(a));
}
__device__ __forceinline__ void mma16816(float* c, const uint32_t* a,
                                         uint32_t b0, uint32_t b1) {
    asm volatile(
        "mma.sync.aligned.m16n8k16.row.col.f32.f16.f16.f32 "
        "{%0,%1,%2,%3}, {%4,%5,%6,%7}, {%8,%9}, {%0,%1,%2,%3};"
        : "+f"(c[0]), "+f"(c[1]), "+f"(c[2]), "+f"(c[3])
        : "r"(a[0]), "r"(a[1]), "r"(a[2]), "r"(a[3]), "r"(b0), "r"(b1));
}
#define CP16(dst, src) \
    asm volatile("cp.async.cg.shared.global [%0], [%1], 16;" :: "r"(dst), "l"(src) : "memory")
#define CP_COMMIT  asm volatile("cp.async.commit_group;" ::: "memory")
#define CP_WAIT0   asm volatile("cp.async.wait_group 0;" ::: "memory")
#define CP_WAIT1   asm volatile("cp.async.wait_group 1;" ::: "memory")

__device__ __forceinline__ uint32_t packh2(float x, float y) {
    __half2 t = __floats2half2_rn(x, y);
    return *(uint32_t*)&t;
}

// ================= flash attention, KVBLK=64 (round-13 verified, untouched) ==
#define QBLK   128
#define KVBLK  64
#define NKVT   (S_/KVBLK)      // 32
#define FO_K   65536           // 2 slots x 32768
#define FO_V   131072          // 2 slots x 32768
#define F_SMEM 196608

__global__ void __launch_bounds__(256)
flash_kernel(const h16* __restrict__ qkvh,
             const h16* __restrict__ vth_g,
             h16* __restrict__ oh_g)
{
    extern __shared__ __align__(128) char sm[];
    const uint32_t sb = smem_u32(sm);
    const int tid = threadIdx.x, wid = tid >> 5, lane = tid & 31;
    const int bh = blockIdx.y;
    const int b = bh >> 3, hd = bh & 7;
    const int q0 = blockIdx.x * QBLK;

    auto load_k = [&](int kv0, uint32_t slot) {      // 64 rows x 512B
        #pragma unroll
        for (int it = 0; it < 8; it++) {
            int c = tid + it * 256;
            int row = c >> 5, kc = c & 31;
            const h16* src = qkvh
                + ((size_t)(b * S_ + kv0 + row) * QKVW_ + 2048 + hd * 256 + kc * 8);
            CP16(slot + row * 512 + (uint32_t)((kc ^ (row & 7)) << 4), src);
        }
    };
    auto load_v = [&](int kv0, uint32_t slot) {      // 256 rows x 128B
        #pragma unroll
        for (int it = 0; it < 8; it++) {
            int c = tid + it * 256;
            int row = c >> 3, kc = c & 7;
            const h16* src = vth_g
                + ((size_t)bh * DH_ * S_ + (size_t)row * S_ + kv0 + kc * 8);
            CP16(slot + row * 128 + (uint32_t)((kc ^ (row & 7)) << 4), src);
        }
    };

    #pragma unroll
    for (int it = 0; it < 16; it++) {                 // Q: 128 rows x 512B
        int c = tid + it * 256;
        int row = c >> 5, kc = c & 31;
        const h16* src = qkvh
            + ((size_t)(b * S_ + q0 + row) * QKVW_ + hd * 256 + kc * 8);
        CP16(sb + row * 512 + (uint32_t)((kc ^ (row & 7)) << 4), src);
    }
    load_k(0, sb + FO_K);
    load_v(0, sb + FO_V);
    CP_COMMIT;
    load_k(KVBLK, sb + FO_K + 32768);
    load_v(KVBLK, sb + FO_V + 32768);
    CP_COMMIT;

    const int wm    = wid * 16;
    const int a_row = wm + (lane & 15);
    const uint32_t a_rowoff = (uint32_t)(a_row * 512);
    const int a_r7  = a_row & 7;
    const int a_hb  = lane >> 4;
    const int b_row = (lane & 7) + ((lane >> 4) & 1) * 8;
    const int b_kb  = (lane >> 3) & 1;

    float o[32][4];
    #pragma unroll
    for (int i = 0; i < 32; i++) { o[i][0]=0.f; o[i][1]=0.f; o[i][2]=0.f; o[i][3]=0.f; }
    float m0 = -1e30f, m1 = -1e30f, l0 = 0.f, l1 = 0.f;

    for (int i = 0; i < NKVT; i++) {
        if (i + 1 < NKVT) { CP_WAIT1; } else { CP_WAIT0; }
        __syncthreads();
        const uint32_t kbs = sb + FO_K + (uint32_t)((i & 1) * 32768);
        const uint32_t vbs = sb + FO_V + (uint32_t)((i & 1) * 32768);

        float s[8][4];
        #pragma unroll
        for (int nt = 0; nt < 8; nt++) { s[nt][0]=0.f; s[nt][1]=0.f; s[nt][2]=0.f; s[nt][3]=0.f; }
        #pragma unroll
        for (int ks = 0; ks < 16; ks++) {
            const uint32_t aq = a_rowoff + (uint32_t)((((2 * ks + a_hb) ^ a_r7) << 4));
            uint32_t ah4[4];
            ldsm_x4(ah4, sb + aq);
            uint32_t kh4[4][4];
            #pragma unroll
            for (int g2 = 0; g2 < 4; g2++) {
                const int row = g2 * 16 + b_row;
                const uint32_t off = (uint32_t)(row * 512 + (((2 * ks + b_kb) ^ (row & 7)) << 4));
                ldsm_x4(kh4[g2], kbs + off);
            }
            #pragma unroll
            for (int nt = 0; nt < 8; nt++)
                mma16816(s[nt], ah4, kh4[nt >> 1][(nt & 1) * 2], kh4[nt >> 1][(nt & 1) * 2 + 1]);
        }

        float mx0 = -1e30f, mx1 = -1e30f;
        #pragma unroll
        for (int nt = 0; nt < 8; nt++) {
            s[nt][0] *= 0.0625f; s[nt][1] *= 0.0625f;
            s[nt][2] *= 0.0625f; s[nt][3] *= 0.0625f;
            mx0 = fmaxf(mx0, fmaxf(s[nt][0], s[nt][1]));
            mx1 = fmaxf(mx1, fmaxf(s[nt][2], s[nt][3]));
        }
        mx0 = fmaxf(mx0, __shfl_xor_sync(0xffffffffu, mx0, 1));
        mx0 = fmaxf(mx0, __shfl_xor_sync(0xffffffffu, mx0, 2));
        mx1 = fmaxf(mx1, __shfl_xor_sync(0xffffffffu, mx1, 1));
        mx1 = fmaxf(mx1, __shfl_xor_sync(0xffffffffu, mx1, 2));
        const float mn0 = fmaxf(m0, mx0), mn1 = fmaxf(m1, mx1);
        const float sc0 = __expf(m0 - mn0), sc1 = __expf(m1 - mn1);
        m0 = mn0; m1 = mn1;
        l0 *= sc0; l1 *= sc1;
        if (sc0 != 1.f || sc1 != 1.f) {
            #pragma unroll
            for (int nt = 0; nt < 32; nt++) {
                o[nt][0] *= sc0; o[nt][1] *= sc0;
                o[nt][2] *= sc1; o[nt][3] *= sc1;
            }
        }
        float rs0 = 0.f, rs1 = 0.f;
        #pragma unroll
        for (int nt = 0; nt < 8; nt++) {
            s[nt][0] = __expf(s[nt][0] - m0);
            s[nt][1] = __expf(s[nt][1] - m0);
            s[nt][2] = __expf(s[nt][2] - m1);
            s[nt][3] = __expf(s[nt][3] - m1);
            rs0 += s[nt][0] + s[nt][1];
            rs1 += s[nt][2] + s[nt][3];
        }
        rs0 += __shfl_xor_sync(0xffffffffu, rs0, 1);
        rs0 += __shfl_xor_sync(0xffffffffu, rs0, 2);
        rs1 += __shfl_xor_sync(0xffffffffu, rs1, 1);
        rs1 += __shfl_xor_sync(0xffffffffu, rs1, 2);
        l0 += rs0; l1 += rs1;

        uint32_t pah[4][4];
        #pragma unroll
        for (int ks = 0; ks < 4; ks++) {
            const int j0 = 2 * ks, j1 = 2 * ks + 1;
            pah[ks][0] = packh2(s[j0][0], s[j0][1]);
            pah[ks][1] = packh2(s[j0][2], s[j0][3]);
            pah[ks][2] = packh2(s[j1][0], s[j1][1]);
            pah[ks][3] = packh2(s[j1][2], s[j1][3]);
        }

        #pragma unroll
        for (int j2 = 0; j2 < 16; j2++) {
            const int row = j2 * 16 + b_row;
            const uint32_t vrow = (uint32_t)(row * 128);
            const int r7 = row & 7;
            #pragma unroll
            for (int ks = 0; ks < 4; ks++) {
                uint32_t vh4[4];
                ldsm_x4(vh4, vbs + vrow + (uint32_t)((((2 * ks + b_kb) ^ r7) << 4)));
                mma16816(o[j2 * 2],     pah[ks], vh4[0], vh4[1]);
                mma16816(o[j2 * 2 + 1], pah[ks], vh4[2], vh4[3]);
            }
        }
        __syncthreads();

        if (i + 2 < NKVT) {
            load_k((i + 2) * KVBLK, sb + FO_K + (uint32_t)((i & 1) * 32768));
            load_v((i + 2) * KVBLK, sb + FO_V + (uint32_t)((i & 1) * 32768));
            CP_COMMIT;
        }
    }

    const float inv0 = 1.f / l0, inv1 = 1.f / l1;
    const int g  = lane >> 2;
    const int t2 = (lane & 3) * 2;
    const size_t base0 = (size_t)(b * S_ + q0 + wm + g) * INNER_ + hd * 256 + t2;
    const size_t base1 = base0 + (size_t)8 * INNER_;
    #pragma unroll
    for (int nt = 0; nt < 32; nt++) {
        *(uint32_t*)&oh_g[base0 + (size_t)nt * 8] = packh2(o[nt][0] * inv0, o[nt][1] * inv0);
        *(uint32_t*)&oh_g[base1 + (size_t)nt * 8] = packh2(o[nt][2] * inv1, o[nt][3] * inv1);
    }
}

// ------- pure fp16 HMMA GEMM, KB=64, cp.async 3-stage, ONE sync/k-block -------
// C = alpha * A @ B^T
#define KB_    64
#define ASTR   144
#define GTILE  (128 * ASTR)       // 18432 B
#define G_SMEM (6 * GTILE)        // 110592 B (A:3 + B:3)

template<int OUT_HALF>
__global__ void __launch_bounds__(256, 2)
gemm_hmma1(const h16* __restrict__ Ah, int lda,
           const h16* __restrict__ Bh, int ldb,
           float* __restrict__ Cf, h16* __restrict__ Ch, int ldc,
           int K, int zdiv,
           long long sA1, long long sA2,
           long long sB1, long long sB2,
           long long sC1, long long sC2,
           const float* __restrict__ bias,
           float alpha, int relu)
{
    extern __shared__ __align__(16) char gsm[];
    const uint32_t uA = smem_u32(gsm);
    const uint32_t uB = uA + 3 * GTILE;

    const int z  = blockIdx.z;
    const int zq = z / zdiv, zr = z % zdiv;
    Ah += (long long)zq * sA1 + (long long)zr * sA2;
    Bh += (long long)zq * sB1 + (long long)zr * sB2;
    const long long coff = (long long)zq * sC1 + (long long)zr * sC2;
    if (Cf) Cf += coff;
    if (Ch) Ch += coff;

    const int bm   = blockIdx.y * 128;
    const int bn   = blockIdx.x * 128;
    const int tid  = threadIdx.x;
    const int wid  = tid >> 5;
    const int lane = tid & 31;
    const int wm   = (wid & 1) * 64;
    const int wn   = (wid >> 1) * 32;

    auto load_tile = [&](int kb, int buf) {
        const uint32_t off = (uint32_t)(buf * GTILE);
        #pragma unroll
        for (int it = 0; it < 4; it++) {
            int c = tid + it * 256;
            int row = c >> 3, kc = c & 7;
            const uint32_t so = (uint32_t)(row * ASTR + kc * 16);
            const int kn = kb * KB_ + kc * 8;
            CP16(uA + off + so, Ah + (long long)(bm + row) * lda + kn);
            CP16(uB + off + so, Bh + (long long)(bn + row) * ldb + kn);
        }
    };

    const uint32_t aBase = (uint32_t)((wm + (lane & 15)) * ASTR + (lane >> 4) * 16);
    const uint32_t bBase = (uint32_t)((wn + (lane & 7) + ((lane >> 4) & 1) * 8) * ASTR
                                      + (lane & 8) * 2);

    float acc[4][4][4];
    #pragma unroll
    for (int mt = 0; mt < 4; mt++)
        #pragma unroll
        for (int nt = 0; nt < 4; nt++)
            #pragma unroll
            for (int i = 0; i < 4; i++) acc[mt][nt][i] = 0.f;

    const int nkb = K / KB_;
    load_tile(0, 0); CP_COMMIT;
    load_tile(1, 1); CP_COMMIT;

    int buf = 0;
    for (int kb = 0; kb < nkb; kb++) {
        if (kb + 1 < nkb) { CP_WAIT1; } else { CP_WAIT0; }
        __syncthreads();           // tile kb visible to all; buf (kb-1)%3 reads done

        if (kb + 2 < nkb) {        // refill the buffer consumed at iter kb-1
            int nb = buf + 2; if (nb >= 3) nb -= 3;
            load_tile(kb + 2, nb);
            CP_COMMIT;
        }

        const uint32_t boff = (uint32_t)(buf * GTILE);
        #pragma unroll
        for (int ks = 0; ks < 4; ks++) {
            const uint32_t ksb = ks * 32;
            uint32_t ah[4][4];
            #pragma unroll
            for (int mt = 0; mt < 4; mt++)
                ldsm_x4(ah[mt], uA + boff + aBase + mt * (16 * ASTR) + ksb);
            uint32_t bh[2][4];
            #pragma unroll
            for (int g = 0; g < 2; g++)
                ldsm_x4(bh[g], uB + boff + bBase + g * (16 * ASTR) + ksb);
            #pragma unroll
            for (int mt = 0; mt < 4; mt++)
                #pragma unroll
                for (int nt = 0; nt < 4; nt++)
                    mma16816(acc[mt][nt], ah[mt],
                             bh[nt >> 1][(nt & 1) * 2], bh[nt >> 1][(nt & 1) * 2 + 1]);
        }
        buf++; if (buf >= 3) buf = 0;
    }

    const int er = lane >> 2;
    const int ec = (lane & 3) * 2;
    #pragma unroll
    for (int mt = 0; mt < 4; mt++) {
        #pragma unroll
        for (int half = 0; half < 2; half++) {
            const int m = bm + wm + mt * 16 + er + half * 8;
            #pragma unroll
            for (int nt = 0; nt < 4; nt++) {
                const int n = bn + wn + nt * 8 + ec;
                float v0 = acc[mt][nt][half * 2 + 0] * alpha;
                float v1 = acc[mt][nt][half * 2 + 1] * alpha;
                if (bias) { v0 += __ldg(&bias[n]); v1 += __ldg(&bias[n + 1]); }
                if (relu) { v0 = fmaxf(v0, 0.f); v1 = fmaxf(v1, 0.f); }
                if (OUT_HALF) {
                    *(uint32_t*)&Ch[(long long)m * ldc + n] = packh2(v0, v1);
                } else {
                    *(float2*)&Cf[(long long)m * ldc + n] = make_float2(v0, v1);
                }
            }
        }
    }
}

// ---------------- warp-per-row split-K reduce + layernorm ----------------
__device__ __forceinline__ float warp_sum(float v) {
    #pragma unroll
    for (int o = 16; o > 0; o >>= 1) v += __shfl_xor_sync(0xffffffffu, v, o);
    return v;
}

__global__ void ln_red_kernel(const float* __restrict__ part, long long pstride,
                              const float* __restrict__ bias,
                              const float* __restrict__ resid,
                              const float* __restrict__ g,
                              const float* __restrict__ b,
                              float* __restrict__ outf,
                              h16* __restrict__ oh)
{
    const int lane = threadIdx.x & 31;
    const int warp = threadIdx.x >> 5;
    const long long row  = (long long)blockIdx.x * 8 + warp;
    const long long base = row * E_;

    float v[8];
    float sum = 0.f;
    #pragma unroll
    for (int j = 0; j < 8; j++) {
        const long long idx = base + lane + j * 32;
        float t = part[idx] + part[idx + pstride]
                + part[idx + 2 * pstride] + part[idx + 3 * pstride];
        if (bias) t += bias[lane + j * 32];
        t += resid[idx];
        v[j] = t;
        sum += t;
    }
    const float mean = warp_sum(sum) * (1.f / E_);
    float vs = 0.f;
    #pragma unroll
    for (int j = 0; j < 8; j++) {
        v[j] -= mean;
        vs += v[j] * v[j];
    }
    const float inv = rsqrtf(warp_sum(vs) * (1.f / E_) + EPS_);
    #pragma unroll
    for (int j = 0; j < 8; j++) {
        const int col = lane + j * 32;
        const float r = v[j] * inv * g[col] + b[col];
        if (outf) outf[base + col] = r;
        if (oh) oh[base + col] = __float2half_rn(r);
    }
}

// ---------------- prep kernels (round-13 form) ----------------
__global__ void split_kernel(const float* __restrict__ in,
                             h16* __restrict__ oh, int n)
{
    int i = blockIdx.x * blockDim.x + threadIdx.x;
    if (i < n) oh[i] = __float2half_rn(in[i]);
}

__device__ __forceinline__ void wconv_tile(const float* W, int R, int C,
                                           h16* oh, int c0, int r0, int tx, int ty)
{
    __shared__ float t[32][33];
    #pragma unroll
    for (int j = 0; j < 4; j++) {
        int r = ty + 8 * j;
        t[r][tx] = W[(long long)(r0 + r) * C + c0 + tx];
    }
    __syncthreads();
    #pragma unroll
    for (int j = 0; j < 4; j++) {
        int r = ty + 8 * j;
        oh[(long long)(c0 + r) * R + r0 + tx] = __float2half_rn(t[tx][r]);
    }
}

__global__ void wconv_qkv(const float* __restrict__ Wq, const float* __restrict__ Wk,
                          const float* __restrict__ Wv, h16* __restrict__ oh)
{
    const float* W = (blockIdx.z == 0) ? Wq : (blockIdx.z == 1) ? Wk : Wv;
    h16* ph = oh + (size_t)blockIdx.z * INNER_ * E_;
    wconv_tile(W, E_, INNER_, ph, blockIdx.x * 32, blockIdx.y * 32,
               threadIdx.x, threadIdx.y);
}

__global__ void wconv_misc(const float* __restrict__ Wo, const float* __restrict__ W1,
                           const float* __restrict__ W2,
                           h16* __restrict__ woT, h16* __restrict__ w1T,
                           h16* __restrict__ w2T)
{
    const float* W; h16* ph; int R, C;
    if (blockIdx.z == 0)      { W = Wo; ph = woT; R = INNER_; C = E_; }
    else if (blockIdx.z == 1) { W = W1; ph = w1T; R = E_; C = DFF_; }
    else                      { W = W2; ph = w2T; R = DFF_; C = E_; }
    if ((int)blockIdx.x * 32 >= C || (int)blockIdx.y * 32 >= R) return;
    wconv_tile(W, R, C, ph, blockIdx.x * 32, blockIdx.y * 32,
               threadIdx.x, threadIdx.y);
}

__global__ void vtrans_kernel(const h16* __restrict__ qkvh,
                              h16* __restrict__ vth)
{
    __shared__ h16 th[32][33];
    const int z = blockIdx.z;
    const int b = z / H_, h = z % H_;
    const int s0 = blockIdx.x * 32;
    const int d0 = blockIdx.y * 32;
    const int tx = threadIdx.x, ty = threadIdx.y;
    const long long ibase = (long long)b * S_ * QKVW_ + 4096 + (long long)h * DH_;
    const long long obase = (long long)z * DH_ * S_;
    #pragma unroll
    for (int j = 0; j < 4; j++) {
        int r = ty + 8 * j;
        th[r][tx] = qkvh[ibase + (long long)(s0 + r) * QKVW_ + d0 + tx];
    }
    __syncthreads();
    #pragma unroll
    for (int j = 0; j < 4; j++) {
        int r = ty + 8 * j;
        vth[obase + (long long)(d0 + r) * S_ + s0 + tx] = th[tx][r];
    }
}

// ---------------- launch ----------------
extern "C" void kernel_launch(void* const* d_in, const int* in_sizes, int n_in,
                              void* d_out, int out_size)
{
    const float* x    = (const float*)d_in[0];
    const float* Wq   = (const float*)d_in[1];
    const float* Wk   = (const float*)d_in[2];
    const float* Wv   = (const float*)d_in[3];
    const float* Wo   = (const float*)d_in[4];
    const float* W1   = (const float*)d_in[5];
    const float* b1   = (const float*)d_in[6];
    const float* W2   = (const float*)d_in[7];
    const float* b2   = (const float*)d_in[8];
    const float* ln1g = (const float*)d_in[9];
    const float* ln1b = (const float*)d_in[10];
    const float* ln2g = (const float*)d_in[11];
    const float* ln2b = (const float*)d_in[12];

    #define SYM(p, s) p; cudaGetSymbolAddress((void**)&p, s)
    h16 *SYM(xh, g_xh);
    h16 *SYM(wqkv, g_wqkvT);
    h16 *SYM(woT, g_woT);
    h16 *SYM(w1T, g_w1T);
    h16 *SYM(w2T, g_w2T);
    h16 *SYM(qkvh, g_qkvh);
    h16 *SYM(vth, g_vth);
    h16 *SYM(oh, g_oh);
    float *SYM(part, g_part);
    float *SYM(hf, g_hf);
    h16 *SYM(hh, g_hh);
    h16 *SYM(ffh, g_ffh);

    cudaFuncSetAttribute(flash_kernel, cudaFuncAttributeMaxDynamicSharedMemorySize, F_SMEM);
    cudaFuncSetAttribute(gemm_hmma1<0>, cudaFuncAttributeMaxDynamicSharedMemorySize, G_SMEM);
    cudaFuncSetAttribute(gemm_hmma1<1>, cudaFuncAttributeMaxDynamicSharedMemorySize, G_SMEM);

    const dim3 blk(256);
    const dim3 tblk(32, 8);
    const long long psz = (long long)BSZ * E_;

    // 1) x -> fp16
    split_kernel<<<(BSZ * E_ + 255) / 256, 256>>>(x, xh, BSZ * E_);
    // 2) QKV weights packed convert-transpose
    { dim3 g(INNER_/32, E_/32, 3); wconv_qkv<<<g, tblk>>>(Wq, Wk, Wv, wqkv); }
    // 3) Wo/W1/W2
    { dim3 g(64, 64, 3); wconv_misc<<<g, tblk>>>(Wo, W1, W2, woT, w1T, w2T); }
    // 4) fused QKV projection: [4096,256] @ [256,6144]
    {
        dim3 grd(QKVW_/128, BSZ/128, 1);
        gemm_hmma1<1><<<grd, blk, G_SMEM>>>(xh, E_, wqkv, E_,
            nullptr, qkvh, QKVW_, E_, 1, 0,0, 0,0, 0,0,
            nullptr, 1.f, 0);
    }
    // 5) V^T per (b,h)
    { dim3 g(S_/32, DH_/32, B_*H_); vtrans_kernel<<<g, tblk>>>(qkvh, vth); }
    // 6) flash attention
    {
        dim3 grd(S_/QBLK, B_*H_);
        flash_kernel<<<grd, blk, F_SMEM>>>(qkvh, vth, oh);
    }
    // 7) Wo split-K x4 -> partials ; LN1 reduce (+x resid)
    {
        dim3 grd(E_/128, BSZ/128, 4);
        gemm_hmma1<0><<<grd, blk, G_SMEM>>>(oh, INNER_, woT, INNER_,
            part, nullptr, E_, INNER_/4, 4,
            0, 512, 0, 512, 0, psz,
            nullptr, 1.f, 0);
        ln_red_kernel<<<BSZ/8, 256>>>(part, psz, nullptr, x, ln1g, ln1b, hf, hh);
    }
    // 8) ff = relu(h @ W1 + b1)
    {
        dim3 grd(DFF_/128, BSZ/128, 1);
        gemm_hmma1<1><<<grd, blk, G_SMEM>>>(hh, E_, w1T, E_,
            nullptr, ffh, DFF_, E_, 1, 0,0, 0,0, 0,0,
            b1, 1.f, 1);
    }
    // 9) FFN2 split-K x4 -> partials ; LN2 reduce (+b2 +h resid) -> out
    {
        dim3 grd(E_/128, BSZ/128, 4);
        gemm_hmma1<0><<<grd, blk, G_SMEM>>>(ffh, DFF_, w2T, DFF_,
            part, nullptr, E_, DFF_/4, 4,
            0, 256, 0, 256, 0, psz,
            nullptr, 1.f, 0);
        ln_red_kernel<<<BSZ/8, 256>>>(part, psz, b2, hf, ln2g, ln2b,
                                      (float*)d_out, nullptr);
    }
}